// round 3
// baseline (speedup 1.0000x reference)
#include <cuda_runtime.h>

// Problem constants (fixed shapes for CIFAR10Net_86096914416128)
#define TT    16
#define NB    32
#define CIN   3
#define HH    32
#define WWID  32
#define COUT  128
#define KW27  27

typedef unsigned long long u64;

// Standardized weights, produced by prep_kernel, consumed by snn_kernel.
__device__ float g_w[COUT * KW27];

// ---------- packed f32x2 helpers (sm_100+ PTX) ----------
__device__ __forceinline__ u64 pack2(float a, float b) {
    u64 r; asm("mov.b64 %0,{%1,%2};" : "=l"(r) : "f"(a), "f"(b)); return r;
}
__device__ __forceinline__ void unpack2(u64 v, float& a, float& b) {
    asm("mov.b64 {%0,%1},%2;" : "=f"(a), "=f"(b) : "l"(v));
}
__device__ __forceinline__ u64 ffma2(u64 a, u64 b, u64 c) {
    asm("fma.rn.f32x2 %0,%1,%2,%0;" : "+l"(c) : "l"(a), "l"(b)); return c;
}
__device__ __forceinline__ u64 fadd2(u64 a, u64 b) {
    u64 r; asm("add.rn.f32x2 %0,%1,%2;" : "=l"(r) : "l"(a), "l"(b)); return r;
}
__device__ __forceinline__ u64 fmul2(u64 a, u64 b) {
    u64 r; asm("mul.rn.f32x2 %0,%1,%2;" : "=l"(r) : "l"(a), "l"(b)); return r;
}

// ---------- weight prep: clip, weight-standardize ----------
// Pure fp32, replicating the reference's elementwise op sequence exactly:
//   mean = (seq-sum v) / 27          (f32)
//   var  = (seq-sum (v-mean)*(v-mean)) / 26   (ddof=1, mul+add, no FMA)
//   w'   = ((v - mean) / sqrt(var + 1e-5)) * nw + nb   (each op rounded f32)
__global__ void prep_kernel(const float* __restrict__ w,
                            const float* __restrict__ nw,
                            const float* __restrict__ nb) {
    int c = threadIdx.x;
    if (c >= COUT) return;
    float v[KW27];
    float s = 0.0f;
#pragma unroll
    for (int i = 0; i < KW27; i++) {
        float t = w[c * KW27 + i];
        t = fminf(4.0f, fmaxf(-4.0f, t));
        v[i] = t;
        s = __fadd_rn(s, t);
    }
    float mean = __fdiv_rn(s, 27.0f);
    float ss = 0.0f;
#pragma unroll
    for (int i = 0; i < KW27; i++) {
        float d = __fsub_rn(v[i], mean);
        ss = __fadd_rn(ss, __fmul_rn(d, d));
    }
    float var   = __fdiv_rn(ss, 26.0f);
    float denom = __fsqrt_rn(__fadd_rn(var, 1e-5f));
    float nwc = nw[c];
    float nbc = nb[c];
#pragma unroll
    for (int i = 0; i < KW27; i++) {
        float std  = __fdiv_rn(__fsub_rn(v[i], mean), denom);
        g_w[c * KW27 + i] = __fadd_rn(__fmul_rn(std, nwc), nbc);
    }
}

// ---------- fused conv3x3 + LIF scan ----------
// Grid: 2048 blocks = b(32) * channel_group(4) * row_pair(16). Block: 256 threads.
// Thread: 1 out-channel, 2 output rows (r0, r0+1) packed as f32x2 lanes, 4 cols.
__global__ void __launch_bounds__(256, 2)
snn_kernel(const float* __restrict__ x,
           const float* __restrict__ thr,
           float* __restrict__ out) {
    // Vertical-pair x tile: [cin][kh][col], .x = row r0-1+kh, .y = row r0+kh.
    // col in [0,34): global w = col-1 (conv halo).
    __shared__ u64 xs[CIN * 3 * 34];

    const int tid = threadIdx.x;
    const int bid = blockIdx.x;
    const int bb  = bid >> 6;          // batch
    const int cg  = (bid >> 4) & 3;    // channel group (32 ch)
    const int rs  = bid & 15;          // row-pair index
    const int r0  = rs * 2;

    const int cl  = tid >> 3;          // channel within group
    const int seg = tid & 7;           // 4-wide w segment
    const int w0  = seg * 4;
    const int c   = cg * 32 + cl;

    // 27 weights duplicated into both f32x2 lanes
    u64 wp[KW27];
#pragma unroll
    for (int i = 0; i < KW27; i++) {
        float wv = g_w[c * KW27 + i];
        wp[i] = pack2(wv, wv);
    }
    const float th = thr[c];
    const float CSG = 1.0f - (float)(1.0 / 3.5);   // (1 - theta_grad), matches ref cast
    const u64 C2 = pack2(CSG, CSG);

    // LIF state: u and sg only (sm/ss are dead in the reference scan)
    u64 u[4]  = {0ull, 0ull, 0ull, 0ull};
    u64 sg[4] = {0ull, 0ull, 0ull, 0ull};

    const int HW = HH * WWID;
    float* ob = out + ((size_t)bb * COUT + c) * HW + (size_t)r0 * WWID + w0;

    for (int t = 0; t < TT; t++) {
        __syncthreads();   // protect smem from previous iteration's readers
        const float* xt = x + (size_t)(t * NB + bb) * (CIN * HW);

        // stage x halo tile as vertical float2 pairs
        for (int idx = tid; idx < CIN * 3 * 34; idx += 256) {
            int cin = idx / 102;
            int rem = idx - cin * 102;
            int jj  = rem / 34;
            int col = rem - jj * 34;
            int gw  = col - 1;
            float va = 0.0f, vb = 0.0f;
            if (gw >= 0 && gw < WWID) {
                int ra = r0 - 1 + jj;       // [-1, 31]
                int rb = r0 + jj;           // [0, 32]
                const float* p = xt + cin * HW + gw;
                if (ra >= 0 && ra < HH) va = p[ra * WWID];
                if (rb < HH)            vb = p[rb * WWID];
            }
            xs[idx] = pack2(va, vb);
        }
        __syncthreads();

        // conv 3x3x3, sequential FMA in (cin, kh, kw) order (matches im2col gemm)
        u64 acc[4] = {0ull, 0ull, 0ull, 0ull};
#pragma unroll
        for (int cin = 0; cin < 3; cin++) {
#pragma unroll
            for (int kh = 0; kh < 3; kh++) {
                const u64* row = &xs[(cin * 3 + kh) * 34 + w0];
                u64 xr[6];
#pragma unroll
                for (int i = 0; i < 6; i++) xr[i] = row[i];
                const int wb = (cin * 3 + kh) * 3;
#pragma unroll
                for (int kw = 0; kw < 3; kw++) {
                    const u64 wv = wp[wb + kw];
#pragma unroll
                    for (int ww = 0; ww < 4; ww++)
                        acc[ww] = ffma2(wv, xr[ww + kw], acc[ww]);
                }
            }
        }

        // LIF update + spike/reset, then store both rows
        float o0[4], o1[4];
#pragma unroll
        for (int k = 0; k < 4; k++) {
            u64 s  = fmul2(fadd2(sg[k], acc[k]), C2);   // sg = (sg + I) * (1 - tg)
            u64 uu = fadd2(u[k], s);                    // u  = u_last + sg
            float ux, uy, sx, sy;
            unpack2(uu, ux, uy);
            unpack2(s,  sx, sy);
            float ox = (ux >= th) ? 1.0f : 0.0f;
            float oy = (uy >= th) ? 1.0f : 0.0f;
            if (ux >= th) { ux = 0.0f; sx = 0.0f; }     // reset on spike
            if (uy >= th) { uy = 0.0f; sy = 0.0f; }
            u[k]  = pack2(ux, uy);
            sg[k] = pack2(sx, sy);
            o0[k] = ox;
            o1[k] = oy;
        }
        float* op = ob + (size_t)t * (NB * COUT * HW);
        *reinterpret_cast<float4*>(op)        = make_float4(o0[0], o0[1], o0[2], o0[3]);
        *reinterpret_cast<float4*>(op + WWID) = make_float4(o1[0], o1[1], o1[2], o1[3]);
    }
}

extern "C" void kernel_launch(void* const* d_in, const int* in_sizes, int n_in,
                              void* d_out, int out_size) {
    const float* x  = (const float*)d_in[0];   // [16,32,3,32,32]
    const float* w  = (const float*)d_in[1];   // [128,3,3,3]
    const float* nw = (const float*)d_in[2];   // [128]
    const float* nb = (const float*)d_in[3];   // [128]
    const float* th = (const float*)d_in[4];   // [128]
    float* out = (float*)d_out;                // [16,32,128,32,32]

    prep_kernel<<<1, 128>>>(w, nw, nb);
    snn_kernel<<<2048, 256>>>(x, th, out);
}

// round 4
// speedup vs baseline: 1.4256x; 1.4256x over previous
#include <cuda_runtime.h>

// Problem constants (fixed shapes for CIFAR10Net_86096914416128)
#define TT    16
#define NB    32
#define CIN   3
#define HH    32
#define WWID  32
#define COUT  128
#define KW27  27

// smem tile geometry (u64 units): 9 rows of 34 logical cols, padded col map
#define ROWS9 9
#define RSTRIDE 38              // 34 cols + 2x 2-u64 gaps -> 304B, 16B aligned
#define TSTRIDE (ROWS9 * RSTRIDE)   // 342 u64 per time step
#define NPAIRS_T (ROWS9 * 34)       // 306 logical pairs per time step

typedef unsigned long long u64;

__device__ float g_w[COUT * KW27];

// ---------- packed f32x2 helpers ----------
__device__ __forceinline__ u64 pack2(float a, float b) {
    u64 r; asm("mov.b64 %0,{%1,%2};" : "=l"(r) : "f"(a), "f"(b)); return r;
}
__device__ __forceinline__ void unpack2(u64 v, float& a, float& b) {
    asm("mov.b64 {%0,%1},%2;" : "=f"(a), "=f"(b) : "l"(v));
}
__device__ __forceinline__ u64 ffma2(u64 a, u64 b, u64 c) {
    asm("fma.rn.f32x2 %0,%1,%2,%0;" : "+l"(c) : "l"(a), "l"(b)); return c;
}
__device__ __forceinline__ u64 fadd2(u64 a, u64 b) {
    u64 r; asm("add.rn.f32x2 %0,%1,%2;" : "=l"(r) : "l"(a), "l"(b)); return r;
}
__device__ __forceinline__ u64 fmul2(u64 a, u64 b) {
    u64 r; asm("mul.rn.f32x2 %0,%1,%2;" : "=l"(r) : "l"(a), "l"(b)); return r;
}

// conflict-free column map: 16B gap every 16 cols
__device__ __forceinline__ int colmap(int c) { return c + 2 * (c >> 4); }

// ---------- weight prep: clip + fp32 weight-standardization (matches ref) ----------
__global__ void prep_kernel(const float* __restrict__ w,
                            const float* __restrict__ nw,
                            const float* __restrict__ nb) {
    int c = threadIdx.x;
    if (c >= COUT) return;
    float v[KW27];
    float s = 0.0f;
#pragma unroll
    for (int i = 0; i < KW27; i++) {
        float t = w[c * KW27 + i];
        t = fminf(4.0f, fmaxf(-4.0f, t));
        v[i] = t;
        s = __fadd_rn(s, t);
    }
    float mean = __fdiv_rn(s, 27.0f);
    float ss = 0.0f;
#pragma unroll
    for (int i = 0; i < KW27; i++) {
        float d = __fsub_rn(v[i], mean);
        ss = __fadd_rn(ss, __fmul_rn(d, d));
    }
    float var   = __fdiv_rn(ss, 26.0f);
    float denom = __fsqrt_rn(__fadd_rn(var, 1e-5f));
    float nwc = nw[c];
    float nbc = nb[c];
#pragma unroll
    for (int i = 0; i < KW27; i++) {
        float std = __fdiv_rn(__fsub_rn(v[i], mean), denom);
        g_w[c * KW27 + i] = __fadd_rn(__fmul_rn(std, nwc), nbc);
    }
}

// ---------- fused conv3x3 + LIF scan, all-t staged, barrier-free mainloop ----------
// Grid: 2048 = b(32) * cgroup(4) * row_pair(16). Block: 256 threads.
// Thread: 1 out-channel, 2 rows packed as f32x2, 4 cols.
__global__ void __launch_bounds__(256, 2)
snn_kernel(const float* __restrict__ x,
           const float* __restrict__ thr,
           float* __restrict__ out) {
    __shared__ __align__(16) u64 xs[TT * TSTRIDE];   // 5472 u64 = 43776 B

    const int tid = threadIdx.x;
    const int bid = blockIdx.x;
    const int bb  = bid >> 6;
    const int cg  = (bid >> 4) & 3;
    const int rs  = bid & 15;
    const int r0  = rs * 2;

    const int cl  = tid >> 3;
    const int seg = tid & 7;
    const int w0  = seg * 4;
    const int c   = cg * 32 + cl;

    // weights duplicated into both f32x2 lanes
    u64 wp[KW27];
#pragma unroll
    for (int i = 0; i < KW27; i++) {
        float wv = g_w[c * KW27 + i];
        wp[i] = pack2(wv, wv);
    }
    const float th = thr[c];
    const float CSG = 1.0f - (float)(1.0 / 3.5);
    const u64 C2 = pack2(CSG, CSG);

    const int HW = HH * WWID;

    // ---- stage ALL 16 time steps as vertical row pairs (one time) ----
    for (int idx = tid; idx < TT * NPAIRS_T; idx += 256) {
        int t   = idx / NPAIRS_T;
        int rem = idx - t * NPAIRS_T;
        int row = rem / 34;              // cin*3 + jj
        int col = rem - row * 34;
        int cin = row / 3;
        int jj  = row - cin * 3;
        int gw  = col - 1;
        float va = 0.0f, vb = 0.0f;
        if (gw >= 0 && gw < WWID) {
            int ra = r0 - 1 + jj;        // [-1, 31]
            int rb = r0 + jj;            // [0, 32]
            const float* p = x + ((size_t)(t * NB + bb) * CIN + cin) * HW + gw;
            if (ra >= 0 && ra < HH) va = p[ra * WWID];
            if (rb < HH)            vb = p[rb * WWID];
        }
        xs[t * TSTRIDE + row * RSTRIDE + colmap(col)] = pack2(va, vb);
    }
    __syncthreads();

    // per-thread chunk offsets within a row (u64 units, 16B aligned)
    const int o0 = colmap(w0);
    const int o1 = colmap(w0 + 2);
    const int o2 = colmap(w0 + 4);

    // LIF state (sm/ss are dead in the reference scan)
    u64 u[4]  = {0ull, 0ull, 0ull, 0ull};
    u64 sg[4] = {0ull, 0ull, 0ull, 0ull};

    float* op = out + ((size_t)bb * COUT + c) * HW + (size_t)r0 * WWID + w0;
    const size_t ostride = (size_t)NB * COUT * HW;   // per-t output stride

#pragma unroll 4
    for (int t = 0; t < TT; t++) {
        const u64* tb = xs + t * TSTRIDE;

        u64 acc[4] = {0ull, 0ull, 0ull, 0ull};
#pragma unroll
        for (int cin = 0; cin < 3; cin++) {
#pragma unroll
            for (int kh = 0; kh < 3; kh++) {
                const u64* rowp = tb + (cin * 3 + kh) * RSTRIDE;
                ulonglong2 p0 = *reinterpret_cast<const ulonglong2*>(rowp + o0);
                ulonglong2 p1 = *reinterpret_cast<const ulonglong2*>(rowp + o1);
                ulonglong2 p2 = *reinterpret_cast<const ulonglong2*>(rowp + o2);
                u64 xr[6] = {p0.x, p0.y, p1.x, p1.y, p2.x, p2.y};
                const int wb = (cin * 3 + kh) * 3;
#pragma unroll
                for (int kw = 0; kw < 3; kw++) {
                    const u64 wv = wp[wb + kw];
#pragma unroll
                    for (int ww = 0; ww < 4; ww++)
                        acc[ww] = ffma2(wv, xr[ww + kw], acc[ww]);
                }
            }
        }

        // LIF update + spike/reset
        float o0v[4], o1v[4];
#pragma unroll
        for (int k = 0; k < 4; k++) {
            u64 s  = fmul2(fadd2(sg[k], acc[k]), C2);   // sg = (sg + I)*(1-tg)
            u64 uu = fadd2(u[k], s);                    // u  = u_last + sg
            float ux, uy, sx, sy;
            unpack2(uu, ux, uy);
            unpack2(s,  sx, sy);
            float ox = (ux >= th) ? 1.0f : 0.0f;
            float oy = (uy >= th) ? 1.0f : 0.0f;
            if (ux >= th) { ux = 0.0f; sx = 0.0f; }
            if (uy >= th) { uy = 0.0f; sy = 0.0f; }
            u[k]  = pack2(ux, uy);
            sg[k] = pack2(sx, sy);
            o0v[k] = ox;
            o1v[k] = oy;
        }
        *reinterpret_cast<float4*>(op)        = make_float4(o0v[0], o0v[1], o0v[2], o0v[3]);
        *reinterpret_cast<float4*>(op + WWID) = make_float4(o1v[0], o1v[1], o1v[2], o1v[3]);
        op += ostride;
    }
}

extern "C" void kernel_launch(void* const* d_in, const int* in_sizes, int n_in,
                              void* d_out, int out_size) {
    const float* x  = (const float*)d_in[0];   // [16,32,3,32,32]
    const float* w  = (const float*)d_in[1];   // [128,3,3,3]
    const float* nw = (const float*)d_in[2];   // [128]
    const float* nb = (const float*)d_in[3];   // [128]
    const float* th = (const float*)d_in[4];   // [128]
    float* out = (float*)d_out;                // [16,32,128,32,32]

    prep_kernel<<<1, 128>>>(w, nw, nb);
    snn_kernel<<<2048, 256>>>(x, th, out);
}